// round 15
// baseline (speedup 1.0000x reference)
#include <cuda_runtime.h>
#include <cuda_bf16.h>
#include <cstdint>

// ---------------- Problem constants ----------------
#define N_ROWS   2048
#define DIM      256
#define T_TRK    256
#define NCOLS_XY 16384             // T*Q
#define BM       128
#define BN       128
#define NCT_XY   (NCOLS_XY / BN)   // 128
#define NCT_XX   (N_ROWS   / BN)   // 16
#define NCT_TOT  (NCT_XY + NCT_XX) // 144
#define KCHUNK   64                // bf16 per K chunk (128B rows, SW128)
#define NCHUNK   (DIM / KCHUNK)    // 4
#define NSTAGE   3
#define NCHNK_FIN 32               // finalize blocks (64 rows each)
#define NTRI     136               // upper-triangle xx tiles (bi <= bj)
#define NBLK     (2048 + NTRI)     // 2184 gemm blocks

// ---------------- Dynamic SMEM layout ----------------
#define A_STAGE  (BM * KCHUNK * 2)          // 16384
#define B_STAGE  (BN * KCHUNK * 2)          // 16384
#define OFF_A    0
#define OFF_B    (NSTAGE * A_STAGE)         // 49152
#define OFF_CTRK (OFF_B + NSTAGE * B_STAGE) // 98304
#define OFF_RTID (OFF_CTRK + BN * 4)        // 98816
#define OFF_REDT (OFF_RTID + BM * 4)        // 99328
#define OFF_REDP (OFF_REDT + BM * 2 * 4)    // 100352
#define OFF_CRT  (OFF_REDP + BM * 2 * 4)    // 101376: colRed tot [128][4]
#define OFF_CRP  (OFF_CRT + BN * 4 * 4)     // 103424: colRed pos [128][4]
#define SMEM_BYTES (OFF_CRP + BN * 4 * 4)   // 105472 (~103KB, 2 CTAs = 206KB)

// ---------------- Device scratch ----------------
static __device__ __nv_bfloat16 g_xb[N_ROWS * DIM];
static __device__ __nv_bfloat16 g_yb[NCOLS_XY * DIM];
static __device__ float g_tot[NCT_TOT * N_ROWS];
static __device__ float g_pos[NCT_TOT * N_ROWS];
static __device__ float g_diag[N_ROWS];
static __device__ float g_pnum[NCHNK_FIN * T_TRK];   // [chunk][track] coalesced
static __device__ float g_pden[NCHNK_FIN * T_TRK];
static __device__ int   g_pcnt[NCHNK_FIN * T_TRK];
static __device__ int   g_tick;

// ---------------- PTX helpers (baseline sm_80+, legal on plain sm_103) ----
__device__ __forceinline__ uint32_t smem_u32(const void* p) {
    uint32_t a;
    asm("{ .reg .u64 t; cvta.to.shared.u64 t, %1; cvt.u32.u64 %0, t; }" : "=r"(a) : "l"(p));
    return a;
}
__device__ __forceinline__ void cp_async16(uint32_t dst, const void* src) {
    asm volatile("cp.async.cg.shared.global [%0], [%1], 16;" :: "r"(dst), "l"(src));
}
#define CP_COMMIT() asm volatile("cp.async.commit_group;" ::: "memory")
#define CP_WAIT(n)  asm volatile("cp.async.wait_group %0;" :: "n"(n) : "memory")

__device__ __forceinline__ void ldsm4(uint32_t r[4], uint32_t addr) {
    asm volatile("ldmatrix.sync.aligned.m8n8.x4.shared.b16 {%0,%1,%2,%3}, [%4];"
                 : "=r"(r[0]), "=r"(r[1]), "=r"(r[2]), "=r"(r[3]) : "r"(addr));
}
__device__ __forceinline__ void mma16816(float c[4], const uint32_t a[4], const uint32_t b[2]) {
    asm volatile(
        "mma.sync.aligned.m16n8k16.row.col.f32.bf16.bf16.f32 "
        "{%0,%1,%2,%3}, {%4,%5,%6,%7}, {%8,%9}, {%0,%1,%2,%3};"
        : "+f"(c[0]), "+f"(c[1]), "+f"(c[2]), "+f"(c[3])
        : "r"(a[0]), "r"(a[1]), "r"(a[2]), "r"(a[3]), "r"(b[0]), "r"(b[1]));
}

// ---------------- fp32 -> bf16 conversion (round-12 proven MLP=2 form) -------
#define NX4 (N_ROWS * DIM / 4)      // 131072
#define NY4 (NCOLS_XY * DIM / 4)    // 1048576
#define NTOT4 (NX4 + NY4)           // 1179648
#define NHALF4 (NTOT4 / 2)          // 589824
__global__ void to_bf16_all(const float* __restrict__ x, const float* __restrict__ y)
{
    int i = blockIdx.x * blockDim.x + threadIdx.x;
    if (i == 0) g_tick = 0;                         // reset finalize ticket each call
    if (i >= NHALF4) return;
    #pragma unroll
    for (int h = 0; h < 2; h++) {
        int j = i + h * NHALF4;
        const float* s; __nv_bfloat16* d; int k;
        if (j < NX4) { s = x; d = g_xb; k = j; }
        else         { s = y; d = g_yb; k = j - NX4; }
        float4 v = reinterpret_cast<const float4*>(s)[k];
        __nv_bfloat162* o = reinterpret_cast<__nv_bfloat162*>(d);
        o[k * 2 + 0] = __floats2bfloat162_rn(v.x, v.y);
        o[k * 2 + 1] = __floats2bfloat162_rn(v.z, v.w);
    }
}

// ---------------- Fused HMMA GEMM + exp + row reductions ----------------
// 1-D grid, NBLK=2184 blocks:
//   id <  2048 : xy tile, bx = id & 15, ct = id >> 4
//   id >= 2048 : xx upper-triangle tile (bi <= bj); off-diagonal tiles emit
//                BOTH row-partials (ct=bj, rows bi) and column-partials
//                (ct=bi, rows bj) via S_xx symmetry.
__global__ __launch_bounds__(256, 2)
void gemm_mma(const int* __restrict__ trk)
{
    extern __shared__ char smem[];
    const uint32_t sA = smem_u32(smem) + OFF_A;
    const uint32_t sB = smem_u32(smem) + OFF_B;
    int*   colTrkS = (int*)(smem + OFF_CTRK);
    int*   rowTidS = (int*)(smem + OFF_RTID);
    float* redT    = (float*)(smem + OFF_REDT);
    float* redP    = (float*)(smem + OFF_REDP);
    float* colRT   = (float*)(smem + OFF_CRT);
    float* colRP   = (float*)(smem + OFF_CRP);

    const int tid = threadIdx.x;
    const int wid = tid >> 5;
    const int lid = tid & 31;
    const int wm = wid & 3;      // warp m: rows wm*32..+31
    const int wn = wid >> 2;     // warp n: cols wn*64..+63

    const int id = blockIdx.x;
    const bool isXX = (id >= 2048);
    int rowBase, colBase, outCt, bi = 0, bj = 0;
    if (!isXX) {
        rowBase = (id & 15) * BM;
        colBase = (id >> 4) * BN;
        outCt   = id >> 4;
    } else {
        int rem = id - 2048;
        while (rem >= NCT_XX - bi) { rem -= NCT_XX - bi; bi++; }   // <=16 iters
        bj = bi + rem;
        rowBase = bi * BM;
        colBase = bj * BN;
        outCt   = NCT_XY + bj;
    }
    const __nv_bfloat16* Bsrc = isXX ? g_xb : g_yb;
    const bool diagBlk = isXX && (bi == bj);
    const bool offDiag = isXX && (bi != bj);

    // FIX (round-14 bug): xy column track is (colBase + tid) & 255 — colBase is
    // a multiple of 128, NOT necessarily of 256, so "tid" alone is wrong for
    // odd xy column tiles.
    if (tid < BN) colTrkS[tid] = isXX ? trk[colBase + tid]
                                      : ((colBase + tid) & (T_TRK - 1));
    if (tid < BM) rowTidS[tid] = trk[rowBase + tid];

    // ---- ldmatrix base offsets at K-step 0 (SW128: c16 ^ (r&7)); step s: ^ (s<<5)
    uint32_t aOff0[2];
    #pragma unroll
    for (int mt = 0; mt < 2; mt++) {
        int r = wm * 32 + mt * 16 + (lid & 7) + ((lid >> 3) & 1) * 8;
        uint32_t c16 = (uint32_t)((lid >> 4) & 1);
        aOff0[mt] = (uint32_t)(r * 128) + ((c16 ^ (uint32_t)(r & 7)) * 16);
    }
    uint32_t bOff0[4];
    #pragma unroll
    for (int ntp = 0; ntp < 4; ntp++) {
        int r = wn * 64 + ntp * 16 + (lid & 7) + ((lid >> 4) & 1) * 8;
        uint32_t c16 = (uint32_t)((lid >> 3) & 1);
        bOff0[ntp] = (uint32_t)(r * 128) + ((c16 ^ (uint32_t)(r & 7)) * 16);
    }

    float c[2][8][4];
    #pragma unroll
    for (int mt = 0; mt < 2; mt++)
        #pragma unroll
        for (int nt = 0; nt < 8; nt++)
            #pragma unroll
            for (int k = 0; k < 4; k++) c[mt][nt][k] = 0.f;

    auto load_chunk = [&](int stage, int kc) {
        const int kEl = kc * KCHUNK;
        uint32_t dstA = sA + (uint32_t)stage * A_STAGE;
        uint32_t dstB = sB + (uint32_t)stage * B_STAGE;
        #pragma unroll
        for (int i = 0; i < 4; i++) {
            int idx = tid + i * 256;            // 0..1023
            int r = idx >> 3, c8 = idx & 7;
            uint32_t off = (uint32_t)(r * 128) + (((uint32_t)c8 ^ (uint32_t)(r & 7)) * 16);
            cp_async16(dstA + off, g_xb + (rowBase + r) * DIM + kEl + c8 * 8);
            cp_async16(dstB + off, Bsrc + (colBase + r) * DIM + kEl + c8 * 8);
        }
    };

    // PDL: wait for the conversion kernel before consuming g_xb/g_yb.
    cudaGridDependencySynchronize();

    load_chunk(0, 0); CP_COMMIT();
    load_chunk(1, 1); CP_COMMIT();

    #pragma unroll
    for (int kc = 0; kc < NCHUNK; kc++) {
        if (kc == NCHUNK - 1) { CP_WAIT(0); } else { CP_WAIT(1); }  // chunk kc arrived
        __syncthreads();                       // orders compute(kc-1) before refill below
        if (kc + 2 < NCHUNK) {
            load_chunk((kc + 2) % NSTAGE, kc + 2);
            CP_COMMIT();
        }

        const uint32_t baseA = sA + (uint32_t)(kc % NSTAGE) * A_STAGE;
        const uint32_t baseB = sB + (uint32_t)(kc % NSTAGE) * B_STAGE;
        #pragma unroll
        for (int s = 0; s < 4; s++) {
            const uint32_t sx = (uint32_t)(s << 5);
            uint32_t a[2][4], b[4][4];
            ldsm4(a[0], baseA + (aOff0[0] ^ sx));
            ldsm4(a[1], baseA + (aOff0[1] ^ sx));
            #pragma unroll
            for (int ntp = 0; ntp < 4; ntp++) ldsm4(b[ntp], baseB + (bOff0[ntp] ^ sx));
            #pragma unroll
            for (int mt = 0; mt < 2; mt++)
                #pragma unroll
                for (int nt = 0; nt < 8; nt++)
                    mma16816(c[mt][nt], a[mt], &b[nt >> 1][(nt & 1) * 2]);
        }
    }

    // ---- epilogue: exp + track-matched row partials (+ column partials for
    //      off-diagonal xx tiles, exploiting S_xx symmetry) ----
    const float INV_TEMP = 1.0f / 0.3f;
    float tot[2][2] = {{0.f, 0.f}, {0.f, 0.f}};
    float pos[2][2] = {{0.f, 0.f}, {0.f, 0.f}};
    int rt[2][2];
    #pragma unroll
    for (int mt = 0; mt < 2; mt++)
        #pragma unroll
        for (int h = 0; h < 2; h++)
            rt[mt][h] = rowTidS[wm * 32 + mt * 16 + (lid >> 2) + 8 * h];

    #pragma unroll
    for (int nt = 0; nt < 8; nt++) {
        const int colL = wn * 64 + nt * 8 + 2 * (lid & 3);
        const int ct0 = colTrkS[colL], ct1 = colTrkS[colL + 1];
        float c0t = 0.f, c1t = 0.f, c0p = 0.f, c1p = 0.f;   // per-nt column accums
        #pragma unroll
        for (int mt = 0; mt < 2; mt++)
            #pragma unroll
            for (int h = 0; h < 2; h++) {
                float e0 = __expf(c[mt][nt][2 * h + 0] * INV_TEMP);
                float e1 = __expf(c[mt][nt][2 * h + 1] * INV_TEMP);
                tot[mt][h] += e0 + e1;
                bool m0 = (ct0 == rt[mt][h]), m1 = (ct1 == rt[mt][h]);
                if (m0) pos[mt][h] += e0;
                if (m1) pos[mt][h] += e1;
                c0t += e0; c1t += e1;          // column sums (match test symmetric)
                if (m0) c0p += e0;
                if (m1) c1p += e1;
                if (diagBlk) {
                    int rowg = rowBase + wm * 32 + mt * 16 + (lid >> 2) + 8 * h;
                    int colg = colBase + colL;
                    if (colg == rowg) g_diag[rowg] = e0;
                    if (colg + 1 == rowg) g_diag[rowg] = e1;
                }
            }
        if (offDiag) {
            // reduce over the 8 lanes sharing this column pair (lid>>2 varies)
            #pragma unroll
            for (int d = 4; d <= 16; d <<= 1) {
                c0t += __shfl_xor_sync(0xffffffffu, c0t, d);
                c1t += __shfl_xor_sync(0xffffffffu, c1t, d);
                c0p += __shfl_xor_sync(0xffffffffu, c0p, d);
                c1p += __shfl_xor_sync(0xffffffffu, c1p, d);
            }
            if (lid < 4) {
                colRT[(colL + 0) * 4 + wm] = c0t;
                colRT[(colL + 1) * 4 + wm] = c1t;
                colRP[(colL + 0) * 4 + wm] = c0p;
                colRP[(colL + 1) * 4 + wm] = c1p;
            }
        }
    }

    #pragma unroll
    for (int mt = 0; mt < 2; mt++)
        #pragma unroll
        for (int h = 0; h < 2; h++) {
            tot[mt][h] += __shfl_xor_sync(0xffffffffu, tot[mt][h], 1);
            tot[mt][h] += __shfl_xor_sync(0xffffffffu, tot[mt][h], 2);
            pos[mt][h] += __shfl_xor_sync(0xffffffffu, pos[mt][h], 1);
            pos[mt][h] += __shfl_xor_sync(0xffffffffu, pos[mt][h], 2);
        }

    if ((lid & 3) == 0) {
        #pragma unroll
        for (int mt = 0; mt < 2; mt++)
            #pragma unroll
            for (int h = 0; h < 2; h++) {
                int r = wm * 32 + mt * 16 + (lid >> 2) + 8 * h;
                redT[r * 2 + wn] = tot[mt][h];
                redP[r * 2 + wn] = pos[mt][h];
            }
    }
    __syncthreads();

    if (tid < BM) {
        g_tot[outCt * N_ROWS + rowBase + tid] = redT[tid * 2] + redT[tid * 2 + 1];
        g_pos[outCt * N_ROWS + rowBase + tid] = redP[tid * 2] + redP[tid * 2 + 1];
    }
    if (offDiag && tid < BN) {
        // transposed contribution: rows = bj tile, column-tile index = bi
        float t4 = colRT[tid * 4 + 0] + colRT[tid * 4 + 1]
                 + colRT[tid * 4 + 2] + colRT[tid * 4 + 3];
        float p4 = colRP[tid * 4 + 0] + colRP[tid * 4 + 1]
                 + colRP[tid * 4 + 2] + colRP[tid * 4 + 3];
        g_tot[(NCT_XY + bi) * N_ROWS + colBase + tid] = t4;
        g_pos[(NCT_XY + bi) * N_ROWS + colBase + tid] = p4;
    }
}

// ---------------- Fused finalize + last-block final reduce --------------------
__global__ __launch_bounds__(256)
void finalize_fused(const int* __restrict__ trk, float* __restrict__ out)
{
    __shared__ float sXT[4][64], sXP[4][64], sQT[4][64], sQP[4][64];
    __shared__ float sN[64], sD[64];
    __shared__ int   sT[64];
    __shared__ bool  isLast;

    const int r = threadIdx.x & 63;
    const int g = threadIdx.x >> 6;
    const int row = blockIdx.x * 64 + r;

    // PDL: wait for gemm before consuming g_tot/g_pos/g_diag.
    cudaGridDependencySynchronize();

    float xyT = 0.f, xyP = 0.f, xxT = 0.f, xxP = 0.f;
    #pragma unroll 4
    for (int c = g * 36; c < (g + 1) * 36; c++) {
        float t = g_tot[c * N_ROWS + row];
        float p = g_pos[c * N_ROWS + row];
        if (c < NCT_XY) { xyT += t; xyP += p; }
        else            { xxT += t; xxP += p; }
    }
    sXT[g][r] = xyT; sXP[g][r] = xyP; sQT[g][r] = xxT; sQP[g][r] = xxP;
    __syncthreads();

    if (g == 0) {
        float aT = sXT[0][r] + sXT[1][r] + sXT[2][r] + sXT[3][r];
        float aP = sXP[0][r] + sXP[1][r] + sXP[2][r] + sXP[3][r];
        float bT = sQT[0][r] + sQT[1][r] + sQT[2][r] + sQT[3][r];
        float bP = sQP[0][r] + sQP[1][r] + sQP[2][r] + sQP[3][r];
        float dg = g_diag[row];
        sN[r] = aP + 0.5f * (bP - dg);
        sD[r] = (aT - aP) + (bT - bP);
        sT[r] = trk[row];
    }
    __syncthreads();

    const int t = threadIdx.x;
    {
        float num = 0.f, den = 0.f; int cnt = 0;
        #pragma unroll 8
        for (int i = 0; i < 64; i++) {
            if (sT[i] == t) { num += sN[i]; den += sD[i]; cnt++; }
        }
        g_pnum[blockIdx.x * T_TRK + t] = num;
        g_pden[blockIdx.x * T_TRK + t] = den;
        g_pcnt[blockIdx.x * T_TRK + t] = cnt;
    }

    __threadfence();
    if (threadIdx.x == 0) isLast = (atomicAdd(&g_tick, 1) == NCHNK_FIN - 1);
    __syncthreads();
    if (!isLast) return;

    float num = 0.f, den = 0.f; int cnt = 0;
    #pragma unroll
    for (int j = 0; j < NCHNK_FIN; j++) {
        num += g_pnum[j * T_TRK + t];
        den += g_pden[j * T_TRK + t];
        cnt += g_pcnt[j * T_TRK + t];
    }
    float loss = 0.f; int pres = 0;
    if (cnt > 0) { pres = 1; loss = -logf(num / (den + num)); }

    __shared__ float sL[T_TRK];
    __shared__ int   sP[T_TRK];
    sL[t] = loss; sP[t] = pres;
    __syncthreads();
    for (int s = T_TRK / 2; s > 0; s >>= 1) {
        if (t < s) { sL[t] += sL[t + s]; sP[t] += sP[t + s]; }
        __syncthreads();
    }
    if (t == 0) out[0] = sL[0] / (float)sP[0];
}

extern "C" void kernel_launch(void* const* d_in, const int* in_sizes, int n_in,
                              void* d_out, int out_size)
{
    const float* x   = (const float*)d_in[0];   // [2048, 256]
    const int*   trk = (const int*)  d_in[1];   // [2048]
    const float* y   = (const float*)d_in[2];   // [256, 64, 256]
    float* out = (float*)d_out;

    static bool init_done = false;
    if (!init_done) {
        cudaFuncSetAttribute(gemm_mma, cudaFuncAttributeMaxDynamicSharedMemorySize, SMEM_BYTES);
        init_done = true;
    }

    to_bf16_all<<<(NHALF4 + 255) / 256, 256>>>(x, y);

    // gemm with programmatic dependent launch (prologue overlaps conversion tail)
    {
        cudaLaunchConfig_t cfg = {};
        cfg.gridDim = dim3(NBLK);                   // 2184: 2048 xy + 136 tri-xx
        cfg.blockDim = dim3(256);
        cfg.dynamicSmemBytes = SMEM_BYTES;
        cfg.stream = 0;
        cudaLaunchAttribute attr[1];
        attr[0].id = cudaLaunchAttributeProgrammaticStreamSerialization;
        attr[0].val.programmaticStreamSerializationAllowed = 1;
        cfg.attrs = attr;
        cfg.numAttrs = 1;
        cudaLaunchKernelEx(&cfg, gemm_mma, trk);
    }

    // finalize with PDL (prologue overlaps gemm tail)
    {
        cudaLaunchConfig_t cfg = {};
        cfg.gridDim = dim3(NCHNK_FIN);
        cfg.blockDim = dim3(256);
        cfg.dynamicSmemBytes = 0;
        cfg.stream = 0;
        cudaLaunchAttribute attr[1];
        attr[0].id = cudaLaunchAttributeProgrammaticStreamSerialization;
        attr[0].val.programmaticStreamSerializationAllowed = 1;
        cfg.attrs = attr;
        cfg.numAttrs = 1;
        cudaLaunchKernelEx(&cfg, finalize_fused, trk, out);
    }
}